// round 15
// baseline (speedup 1.0000x reference)
#include <cuda_runtime.h>
#include <cuda_fp16.h>
#include <cstdint>

#define TDIM 1024
#define JDIM 128
#define BDIM 32
#define DDIM 256
#define VNEG -1e30f
#define NTILE 16          // t-tiles per batch (64 rows each)

// ---------------- scratch ----------------
__device__ float g_q2c[BDIM * DDIM];
__device__ __align__(16) unsigned char g_qh[BDIM * 65536];   // preconverted swizzled Q fp16
__device__ float g_qproj[BDIM * JDIM];
__device__ float g_pvec[BDIM * NTILE * DDIM];   // per-tile weighted ctx partials
__device__ float g_pls[BDIM * NTILE * 2];       // per-tile (L, S)

// ---------------- PTX helpers ----------------
__device__ __forceinline__ void ldsm4(uint32_t* r, uint32_t addr) {
    asm volatile("ldmatrix.sync.aligned.m8n8.x4.shared.b16 {%0,%1,%2,%3}, [%4];"
        : "=r"(r[0]), "=r"(r[1]), "=r"(r[2]), "=r"(r[3]) : "r"(addr));
}
__device__ __forceinline__ void ldsm4t(uint32_t* r, uint32_t addr) {
    asm volatile("ldmatrix.sync.aligned.m8n8.x4.trans.shared.b16 {%0,%1,%2,%3}, [%4];"
        : "=r"(r[0]), "=r"(r[1]), "=r"(r[2]), "=r"(r[3]) : "r"(addr));
}
__device__ __forceinline__ void mma_f16(float* d, const uint32_t* a, uint32_t b0, uint32_t b1) {
    asm volatile("mma.sync.aligned.m16n8k16.row.col.f32.f16.f16.f32 "
        "{%0,%1,%2,%3}, {%4,%5,%6,%7}, {%8,%9}, {%0,%1,%2,%3};"
        : "+f"(d[0]), "+f"(d[1]), "+f"(d[2]), "+f"(d[3])
        : "r"(a[0]), "r"(a[1]), "r"(a[2]), "r"(a[3]), "r"(b0), "r"(b1));
}
__device__ __forceinline__ uint32_t smem_to_u32(const void* p) {
    uint32_t a;
    asm("{ .reg .u64 t; cvta.to.shared.u64 t, %1; cvt.u32.u64 %0, t; }" : "=r"(a) : "l"(p));
    return a;
}
__device__ __forceinline__ void cp_async16(uint32_t dst, const void* src) {
    asm volatile("cp.async.cg.shared.global [%0], [%1], 16;" :: "r"(dst), "l"(src));
}
#define CP_COMMIT() asm volatile("cp.async.commit_group;" ::: "memory")
#define CP_WAIT(n)  asm volatile("cp.async.wait_group %0;" :: "n"(n) : "memory")

__device__ __forceinline__ uint32_t packh(float a, float b) {
    __half2 h = __floats2half2_rn(a, b);     // a -> low 16 bits
    return *reinterpret_cast<uint32_t*>(&h);
}

// streaming (evict-first) stores: G is write-once, keep ctx resident in L2
__device__ __forceinline__ void stcs2(float* p, float x, float y) {
    asm volatile("st.global.cs.v2.f32 [%0], {%1, %2};" :: "l"(p), "f"(x), "f"(y) : "memory");
}
__device__ __forceinline__ void stcs4(float* p, float4 v) {
    asm volatile("st.global.cs.v4.f32 [%0], {%1, %2, %3, %4};"
        :: "l"(p), "f"(v.x), "f"(v.y), "f"(v.z), "f"(v.w) : "memory");
}

// swizzled byte offsets (XOR within 128B blocks)
__device__ __forceinline__ uint32_t sw512(int row, int colb) {   // 512B rows (Q: 256 fp16)
    return (uint32_t)(row * 512 + (colb & ~127) + ((colb & 127) ^ ((row & 7) << 4)));
}
__device__ __forceinline__ uint32_t sw256(int row, int colb) {   // 256B rows (cw chunk: 128 fp16)
    return (uint32_t)(row * 256 + (colb & ~127) + ((colb & 127) ^ ((row & 7) << 4)));
}

// dynamic smem layout (bytes): QHI 64KB, CWHI 16KB (64 rows), CTXRAW 32KB (64 rows)
// PART (q2c partials, 32 slots x 258 floats = 33KB) overlays dead CWHI+CTXRAW.
// Total 112KB -> 2 blocks/SM (224KB of 228KB), regs uncapped (128thr*2*~190 << 64K).
#define QHI_OFF    0
#define CWHI_OFF   65536
#define CTXRAW_OFF 81920
#define PART_OFF   65536
#define SMEM_DYN   114688

// ---- k0: preconvert Q -> swizzled fp16 (per batch) + qproj ---------------
__global__ __launch_bounds__(256, 1)
void bidaf_k0(const float* __restrict__ qst, const float* __restrict__ att_w)
{
    const int b  = blockIdx.y;
    const int j  = blockIdx.x * 32 + (threadIdx.x >> 3);
    const int d0 = (threadIdx.x & 7) * 32;
    const float* src = qst + ((size_t)j * BDIM + b) * DDIM + d0;
    unsigned char* dst = g_qh + (size_t)b * 65536;
    float qp = 0.f;
    #pragma unroll
    for (int i = 0; i < 4; ++i) {
        float v[8];
        *(float4*)(v)     = *(const float4*)(src + i * 8);
        *(float4*)(v + 4) = *(const float4*)(src + i * 8 + 4);
        #pragma unroll
        for (int e = 0; e < 8; ++e) qp += v[e] * __ldg(att_w + 256 + d0 + i * 8 + e);
        uint4 hv = make_uint4(packh(v[0], v[1]), packh(v[2], v[3]),
                              packh(v[4], v[5]), packh(v[6], v[7]));
        *(uint4*)(dst + sw512(j, d0 * 2 + i * 16)) = hv;
    }
    qp += __shfl_xor_sync(0xffffffffu, qp, 1);
    qp += __shfl_xor_sync(0xffffffffu, qp, 2);
    qp += __shfl_xor_sync(0xffffffffu, qp, 4);
    if ((threadIdx.x & 7) == 0) g_qproj[b * JDIM + j] = qp;
}

__global__ __launch_bounds__(128, 2)
void bidaf_k1_mma(const float* __restrict__ ctx, const float* __restrict__ qst,
                  const int* __restrict__ con_lens, const int* __restrict__ qu_lens,
                  const float* __restrict__ att_w, float* __restrict__ G)
{
    extern __shared__ char U[];
    __shared__ float s_wc[256], s_wcq[256];
    __shared__ float s_qproj[128], s_cproj[64];
    __shared__ float s_m[64];

    const uint32_t ub = smem_to_u32(U);
    const int tid  = threadIdx.x;
    const int lane = tid & 31;
    const int warp = tid >> 5;      // 0..3
    const int b    = blockIdx.y;
    const int tile = blockIdx.x;
    const int t0   = tile * 64;
    const int clen = con_lens[b];
    const int qlen = qu_lens[b];

    s_wc[tid]        = att_w[tid];
    s_wc[tid + 128]  = att_w[tid + 128];
    s_wcq[tid]       = att_w[512 + tid];
    s_wcq[tid + 128] = att_w[640 + tid];
    s_qproj[tid]     = g_qproj[b * JDIM + tid];
    __syncthreads();   // weights/qproj visible before consumption

    // ---- async copy of preconverted Q (swizzle preserved byte-for-byte) -----
    {
        const unsigned char* src = g_qh + (size_t)b * 65536;
        #pragma unroll
        for (int i = 0; i < 32; ++i) {
            const uint32_t off = (uint32_t)(i * 128 + tid) * 16u;
            cp_async16(ub + QHI_OFF + off, src + off);
        }
    }
    CP_COMMIT();   // group: Q

    // ---- async prefetch of raw fp32 ctx chunk 1 into CTXRAW -----------------
    {
        #pragma unroll
        for (int k = 0; k < 16; ++k) {
            const int row = k * 4 + warp;
            const float* src = ctx + ((size_t)(t0 + row) * BDIM + b) * DDIM + 128 + lane * 4;
            cp_async16(ub + CTXRAW_OFF + (uint32_t)(row * 512 + lane * 16), src);
        }
    }
    CP_COMMIT();   // group: ctx chunk 1

    // ---- chunk 0 staging: warp=row, lane=4 consecutive floats (coalesced) ---
    #pragma unroll
    for (int k = 0; k < 16; ++k) {
        const int row = k * 4 + warp;
        const float* src = ctx + ((size_t)(t0 + row) * BDIM + b) * DDIM + lane * 4;
        float4 v = *(const float4*)src;
        const float* wc  = s_wc  + lane * 4;
        const float* wcq = s_wcq + lane * 4;
        float dot = v.x * wc[0] + v.y * wc[1] + v.z * wc[2] + v.w * wc[3];
        float m0 = v.x * wcq[0], m1 = v.y * wcq[1], m2 = v.z * wcq[2], m3 = v.w * wcq[3];
        const uint32_t off = sw256(row, lane * 8);
        *(uint2*)(U + CWHI_OFF + off) = make_uint2(packh(m0, m1), packh(m2, m3));
        #pragma unroll
        for (int o = 16; o > 0; o >>= 1) dot += __shfl_xor_sync(0xffffffffu, dot, o);
        if (lane == 0) s_cproj[row] = dot;
    }

    // fragment address components
    const int rb = warp * 16;
    const uint32_t a_row  = (uint32_t)(rb + (lane & 15));
    const uint32_t a_cb   = (uint32_t)((lane >> 4) * 16);
    const uint32_t b1_row = (uint32_t)(((lane >> 4) << 3) + (lane & 7));   // GEMM1 B
    const uint32_t b1_cb  = (uint32_t)(((lane >> 3) & 1) * 16);
    const uint32_t b2_row = (uint32_t)(lane & 15);                          // GEMM2 B (trans)
    const uint32_t b2_cb  = (uint32_t)((lane >> 4) * 16);

    float acc[16][4];
    #pragma unroll
    for (int n = 0; n < 16; ++n)
        #pragma unroll
        for (int e = 0; e < 4; ++e) acc[n][e] = 0.f;

    CP_WAIT(1);        // Q image resident (ctx chunk 1 may still be in flight)
    __syncthreads();

    // ---------------- GEMM1 chunk 0 (single-pass cw-hi) ----------------------
    #pragma unroll
    for (int ks = 0; ks < 8; ++ks) {
        uint32_t ah[4];
        ldsm4(ah, ub + CWHI_OFF + sw256((int)a_row, ks * 32 + (int)a_cb));
        #pragma unroll
        for (int nb2 = 0; nb2 < 8; ++nb2) {
            uint32_t bf[4];
            ldsm4(bf, ub + QHI_OFF + sw512(nb2 * 16 + (int)b1_row, ks * 32 + (int)b1_cb));
            mma_f16(acc[nb2 * 2],     ah, bf[0], bf[1]);
            mma_f16(acc[nb2 * 2 + 1], ah, bf[2], bf[3]);
        }
    }
    __syncthreads();   // chunk0 mma done reading CW
    CP_WAIT(0);        // raw ctx chunk 1 resident

    // ---- chunk 1 conversion from smem (no DRAM latency) ---------------------
    #pragma unroll
    for (int k = 0; k < 16; ++k) {
        const int row = k * 4 + warp;
        float4 v = *(const float4*)(U + CTXRAW_OFF + row * 512 + lane * 16);
        const float* wc  = s_wc  + 128 + lane * 4;
        const float* wcq = s_wcq + 128 + lane * 4;
        float dot = v.x * wc[0] + v.y * wc[1] + v.z * wc[2] + v.w * wc[3];
        float m0 = v.x * wcq[0], m1 = v.y * wcq[1], m2 = v.z * wcq[2], m3 = v.w * wcq[3];
        const uint32_t off = sw256(row, lane * 8);
        *(uint2*)(U + CWHI_OFF + off) = make_uint2(packh(m0, m1), packh(m2, m3));
        #pragma unroll
        for (int o = 16; o > 0; o >>= 1) dot += __shfl_xor_sync(0xffffffffu, dot, o);
        if (lane == 0) s_cproj[row] += dot;
    }
    __syncthreads();

    // ---------------- GEMM1 chunk 1 ------------------------------------------
    #pragma unroll
    for (int ks = 0; ks < 8; ++ks) {
        uint32_t ah[4];
        ldsm4(ah, ub + CWHI_OFF + sw256((int)a_row, ks * 32 + (int)a_cb));
        #pragma unroll
        for (int nb2 = 0; nb2 < 8; ++nb2) {
            uint32_t bf[4];
            ldsm4(bf, ub + QHI_OFF + sw512(nb2 * 16 + (int)b1_row, 256 + ks * 32 + (int)b1_cb));
            mma_f16(acc[nb2 * 2],     ah, bf[0], bf[1]);
            mma_f16(acc[nb2 * 2 + 1], ah, bf[2], bf[3]);
        }
    }
    __syncthreads();

    // ---------------- softmax over j in registers -----------------------------
    const int r0 = rb + (lane >> 2);
    const int r1 = r0 + 8;
    const float cpv0 = s_cproj[r0], cpv1 = s_cproj[r1];
    const bool tval0 = (t0 + r0) < clen;
    const bool tval1 = (t0 + r1) < clen;

    float mx0 = -3.4e38f, mx1 = -3.4e38f;
    #pragma unroll
    for (int nb = 0; nb < 16; ++nb) {
        const int j0 = nb * 8 + (lane & 3) * 2;
        const float2 qp = *(const float2*)&s_qproj[j0];
        const bool jv0 = j0 < qlen, jv1 = (j0 + 1) < qlen;
        float s0 = (tval0 && jv0) ? acc[nb][0] + cpv0 + qp.x : VNEG;
        float s1 = (tval0 && jv1) ? acc[nb][1] + cpv0 + qp.y : VNEG;
        float s2 = (tval1 && jv0) ? acc[nb][2] + cpv1 + qp.x : VNEG;
        float s3 = (tval1 && jv1) ? acc[nb][3] + cpv1 + qp.y : VNEG;
        acc[nb][0] = s0; acc[nb][1] = s1; acc[nb][2] = s2; acc[nb][3] = s3;
        mx0 = fmaxf(mx0, fmaxf(s0, s1));
        mx1 = fmaxf(mx1, fmaxf(s2, s3));
    }
    mx0 = fmaxf(mx0, __shfl_xor_sync(0xffffffffu, mx0, 1));
    mx0 = fmaxf(mx0, __shfl_xor_sync(0xffffffffu, mx0, 2));
    mx1 = fmaxf(mx1, __shfl_xor_sync(0xffffffffu, mx1, 1));
    mx1 = fmaxf(mx1, __shfl_xor_sync(0xffffffffu, mx1, 2));

    if ((lane & 3) == 0) { s_m[r0] = mx0; s_m[r1] = mx1; }

    float sm0 = 0.f, sm1 = 0.f;
    #pragma unroll
    for (int nb = 0; nb < 16; ++nb) {
        acc[nb][0] = __expf(acc[nb][0] - mx0); sm0 += acc[nb][0];
        acc[nb][1] = __expf(acc[nb][1] - mx0); sm0 += acc[nb][1];
        acc[nb][2] = __expf(acc[nb][2] - mx1); sm1 += acc[nb][2];
        acc[nb][3] = __expf(acc[nb][3] - mx1); sm1 += acc[nb][3];
    }
    sm0 += __shfl_xor_sync(0xffffffffu, sm0, 1);
    sm0 += __shfl_xor_sync(0xffffffffu, sm0, 2);
    sm1 += __shfl_xor_sync(0xffffffffu, sm1, 1);
    sm1 += __shfl_xor_sync(0xffffffffu, sm1, 2);
    const float iv0 = 1.f / sm0, iv1 = 1.f / sm1;

    __syncthreads();   // s_m complete

    // ---- tile-level max/sum for split softmax over t (warp-redundant) -------
    float Lb, Sw;
    {
        float v0 = s_m[lane], v1 = s_m[lane + 32];
        Lb = fmaxf(v0, v1);
        #pragma unroll
        for (int o = 16; o > 0; o >>= 1) Lb = fmaxf(Lb, __shfl_xor_sync(0xffffffffu, Lb, o));
        Sw = __expf(v0 - Lb) + __expf(v1 - Lb);
        #pragma unroll
        for (int o = 16; o > 0; o >>= 1) Sw += __shfl_xor_sync(0xffffffffu, Sw, o);
    }
    const float w0 = __expf(mx0 - Lb);
    const float w1 = __expf(mx1 - Lb);
    if (tid == 0) {
        g_pls[(b * NTILE + tile) * 2]     = Lb;
        g_pls[(b * NTILE + tile) * 2 + 1] = Sw;
    }

    // ---------------- pack P into A-fragments (hi fp16 only) ------------------
    uint32_t Ah[8][4];
    #pragma unroll
    for (int ks = 0; ks < 8; ++ks) {
        float p00 = acc[2 * ks][0] * iv0,     p01 = acc[2 * ks][1] * iv0;
        float p10 = acc[2 * ks][2] * iv1,     p11 = acc[2 * ks][3] * iv1;
        float p20 = acc[2 * ks + 1][0] * iv0, p21 = acc[2 * ks + 1][1] * iv0;
        float p30 = acc[2 * ks + 1][2] * iv1, p31 = acc[2 * ks + 1][3] * iv1;
        Ah[ks][0] = packh(p00, p01);
        Ah[ks][1] = packh(p10, p11);
        Ah[ks][2] = packh(p20, p21);
        Ah[ks][3] = packh(p30, p31);
    }

    // ---------------- GEMM2: c2q = Ph . Q, two 128-d halves -------------------
    const float tv0 = tval0 ? 1.f : 0.f;
    const float tv1 = tval1 ? 1.f : 0.f;
    const float* crow0 = ctx + ((size_t)(t0 + r0) * BDIM + b) * DDIM;
    const float* crow1 = ctx + ((size_t)(t0 + r1) * BDIM + b) * DDIM;
    float* grow0 = G + ((size_t)b * TDIM + t0 + r0) * (4 * DDIM);
    float* grow1 = G + ((size_t)b * TDIM + t0 + r1) * (4 * DDIM);
    const uint32_t slot = (uint32_t)(warp * 8 + (lane >> 2));   // 0..31

    #pragma unroll 1
    for (int h = 0; h < 2; ++h) {
        #pragma unroll
        for (int n = 0; n < 16; ++n)
            #pragma unroll
            for (int e = 0; e < 4; ++e) acc[n][e] = 0.f;

        #pragma unroll
        for (int ks = 0; ks < 8; ++ks) {
            #pragma unroll
            for (int nb2 = 0; nb2 < 8; ++nb2) {
                uint32_t bf[4];
                ldsm4t(bf, ub + QHI_OFF + sw512(ks * 16 + (int)b2_row, h * 256 + nb2 * 32 + (int)b2_cb));
                mma_f16(acc[nb2 * 2],     Ah[ks], bf[0], bf[1]);
                mma_f16(acc[nb2 * 2 + 1], Ah[ks], bf[2], bf[3]);
            }
        }

        // epilogue for this d-half: G cols [0,768) + q2c partial store
        #pragma unroll
        for (int nb = 0; nb < 16; ++nb) {
            const int d = h * 128 + nb * 8 + (lane & 3) * 2;
            float2 c0 = *(const float2*)(crow0 + d);
            float2 c1 = *(const float2*)(crow1 + d);
            float2 q0 = make_float2(acc[nb][0], acc[nb][1]);
            float2 q1 = make_float2(acc[nb][2], acc[nb][3]);
            stcs2(grow0 + d,       c0.x * tv0,        c0.y * tv0);
            stcs2(grow0 + 256 + d, q0.x * tv0,        q0.y * tv0);
            stcs2(grow0 + 512 + d, c0.x * q0.x * tv0, c0.y * q0.y * tv0);
            stcs2(grow1 + d,       c1.x * tv1,        c1.y * tv1);
            stcs2(grow1 + 256 + d, q1.x * tv1,        q1.y * tv1);
            stcs2(grow1 + 512 + d, c1.x * q1.x * tv1, c1.y * q1.y * tv1);
            float2 vp;
            vp.x = w0 * c0.x + w1 * c1.x;
            vp.y = w0 * c0.y + w1 * c1.y;
            *(float2*)(U + PART_OFF + (slot * 258 + (uint32_t)d) * 4u) = vp;
        }
    }

    // ---- reduce q2c partials over 32 slots; write per-tile vector -----------
    __syncthreads();
    float a0 = 0.f, a1 = 0.f;
    #pragma unroll
    for (int s = 0; s < 32; ++s) {
        a0 += *(const float*)(U + PART_OFF + ((uint32_t)s * 258 + (uint32_t)tid) * 4u);
        a1 += *(const float*)(U + PART_OFF + ((uint32_t)s * 258 + (uint32_t)tid + 128u) * 4u);
    }
    g_pvec[((size_t)(b * NTILE + tile)) * DDIM + tid]       = a0;
    g_pvec[((size_t)(b * NTILE + tile)) * DDIM + tid + 128] = a1;
}

// ---- k2: combine per-tile partials -> q2c (split softmax over t) ----
__global__ __launch_bounds__(256, 1)
void bidaf_k2(int dummy)
{
    const int b = blockIdx.x;
    const int tid = threadIdx.x;
    float L[NTILE], S[NTILE];
    #pragma unroll
    for (int i = 0; i < NTILE; ++i) {
        L[i] = g_pls[(b * NTILE + i) * 2];
        S[i] = g_pls[(b * NTILE + i) * 2 + 1];
    }
    float M = L[0];
    #pragma unroll
    for (int i = 1; i < NTILE; ++i) M = fmaxf(M, L[i]);
    float denom = 0.f, sc[NTILE];
    #pragma unroll
    for (int i = 0; i < NTILE; ++i) { sc[i] = __expf(L[i] - M); denom += sc[i] * S[i]; }
    float acc = 0.f;
    #pragma unroll
    for (int i = 0; i < NTILE; ++i)
        acc += sc[i] * g_pvec[((size_t)(b * NTILE + i)) * DDIM + tid];
    g_q2c[b * DDIM + tid] = acc / denom;
}

// ---- k3: G[:, 768:1024) = ctx * q2c * t_valid ----
__global__ void bidaf_k3(const float* __restrict__ ctx, const int* __restrict__ con_lens,
                         float* __restrict__ G)
{
    const int gid = blockIdx.x * 256 + threadIdx.x;
    const int r = gid >> 6;
    const int d = (gid & 63) * 4;
    const int b = r >> 10;
    const int t = r & (TDIM - 1);
    const float tv = (t < con_lens[b]) ? 1.f : 0.f;
    float4 c = *(const float4*)&ctx[((size_t)t * BDIM + b) * DDIM + d];
    float4 q = *(const float4*)&g_q2c[b * DDIM + d];
    float4 o;
    o.x = c.x * q.x * tv; o.y = c.y * q.y * tv;
    o.z = c.z * q.z * tv; o.w = c.w * q.w * tv;
    stcs4(&G[(size_t)r * (4 * DDIM) + 3 * DDIM + d], o);
}

extern "C" void kernel_launch(void* const* d_in, const int* in_sizes, int n_in,
                              void* d_out, int out_size)
{
    const float* ctx = (const float*)d_in[0];
    const float* qst = (const float*)d_in[1];
    const int*   cl  = (const int*)d_in[2];
    const int*   ql  = (const int*)d_in[3];
    const float* aw  = (const float*)d_in[4];
    float* G = (float*)d_out;

    cudaFuncSetAttribute(bidaf_k1_mma, cudaFuncAttributeMaxDynamicSharedMemorySize, SMEM_DYN);

    bidaf_k0<<<dim3(4, BDIM), 256>>>(qst, aw);
    dim3 g1(NTILE, BDIM);
    bidaf_k1_mma<<<g1, 128, SMEM_DYN>>>(ctx, qst, cl, ql, aw, G);
    bidaf_k2<<<BDIM, 256>>>(0);
    bidaf_k3<<<(BDIM * TDIM * DDIM / 4) / 256, 256>>>(ctx, cl, G);
}

// round 16
// speedup vs baseline: 1.1419x; 1.1419x over previous
#include <cuda_runtime.h>
#include <cuda_fp16.h>
#include <cstdint>

#define TDIM 1024
#define JDIM 128
#define BDIM 32
#define DDIM 256
#define VNEG -1e30f

// ---------------- scratch ----------------
__device__ float g_q2c[BDIM * DDIM];
__device__ __align__(16) unsigned char g_qh[BDIM * 65536];   // preconverted swizzled Q fp16
__device__ float g_qproj[BDIM * JDIM];
__device__ float g_pvec[BDIM * 8 * DDIM];    // per-tile weighted ctx partials
__device__ float g_pls[BDIM * 8 * 2];        // per-tile (L, S)

// ---------------- PTX helpers ----------------
__device__ __forceinline__ void ldsm4(uint32_t* r, uint32_t addr) {
    asm volatile("ldmatrix.sync.aligned.m8n8.x4.shared.b16 {%0,%1,%2,%3}, [%4];"
        : "=r"(r[0]), "=r"(r[1]), "=r"(r[2]), "=r"(r[3]) : "r"(addr));
}
__device__ __forceinline__ void ldsm4t(uint32_t* r, uint32_t addr) {
    asm volatile("ldmatrix.sync.aligned.m8n8.x4.trans.shared.b16 {%0,%1,%2,%3}, [%4];"
        : "=r"(r[0]), "=r"(r[1]), "=r"(r[2]), "=r"(r[3]) : "r"(addr));
}
__device__ __forceinline__ void mma_f16(float* d, const uint32_t* a, uint32_t b0, uint32_t b1) {
    asm volatile("mma.sync.aligned.m16n8k16.row.col.f32.f16.f16.f32 "
        "{%0,%1,%2,%3}, {%4,%5,%6,%7}, {%8,%9}, {%0,%1,%2,%3};"
        : "+f"(d[0]), "+f"(d[1]), "+f"(d[2]), "+f"(d[3])
        : "r"(a[0]), "r"(a[1]), "r"(a[2]), "r"(a[3]), "r"(b0), "r"(b1));
}
__device__ __forceinline__ uint32_t smem_to_u32(const void* p) {
    uint32_t a;
    asm("{ .reg .u64 t; cvta.to.shared.u64 t, %1; cvt.u32.u64 %0, t; }" : "=r"(a) : "l"(p));
    return a;
}
__device__ __forceinline__ void cp_async16(uint32_t dst, const void* src) {
    asm volatile("cp.async.cg.shared.global [%0], [%1], 16;" :: "r"(dst), "l"(src));
}
#define CP_COMMIT() asm volatile("cp.async.commit_group;" ::: "memory")
#define CP_WAIT(n)  asm volatile("cp.async.wait_group %0;" :: "n"(n) : "memory")

__device__ __forceinline__ uint32_t packh(float a, float b) {
    __half2 h = __floats2half2_rn(a, b);     // a -> low 16 bits
    return *reinterpret_cast<uint32_t*>(&h);
}

// streaming (evict-first) stores: G is write-once, keep ctx resident in L2
__device__ __forceinline__ void stcs2(float* p, float x, float y) {
    asm volatile("st.global.cs.v2.f32 [%0], {%1, %2};" :: "l"(p), "f"(x), "f"(y) : "memory");
}
__device__ __forceinline__ void stcs4(float* p, float4 v) {
    asm volatile("st.global.cs.v4.f32 [%0], {%1, %2, %3, %4};"
        :: "l"(p), "f"(v.x), "f"(v.y), "f"(v.z), "f"(v.w) : "memory");
}

// swizzled byte offsets (XOR within 128B blocks)
__device__ __forceinline__ uint32_t sw512(int row, int colb) {   // 512B rows (Q: 256 fp16)
    return (uint32_t)(row * 512 + (colb & ~127) + ((colb & 127) ^ ((row & 7) << 4)));
}
__device__ __forceinline__ uint32_t sw256(int row, int colb) {   // 256B rows (cw chunk: 128 fp16)
    return (uint32_t)(row * 256 + (colb & ~127) + ((colb & 127) ^ ((row & 7) << 4)));
}

// dynamic smem layout (bytes): QHI 64KB, CWHI 32KB, CTXRAW 64KB
// PART (q2c partials, 64 slots x 258 floats = 66KB) overlays dead CWHI+CTXRAW.
#define QHI_OFF    0
#define CWHI_OFF   65536
#define CTXRAW_OFF 98304
#define PART_OFF   65536
#define SMEM_DYN   163840

// ---- k0: preconvert Q -> swizzled fp16 (per batch) + qproj ---------------
__global__ __launch_bounds__(256, 1)
void bidaf_k0(const float* __restrict__ qst, const float* __restrict__ att_w)
{
    const int b  = blockIdx.y;
    const int j  = blockIdx.x * 32 + (threadIdx.x >> 3);
    const int d0 = (threadIdx.x & 7) * 32;
    const float* src = qst + ((size_t)j * BDIM + b) * DDIM + d0;
    unsigned char* dst = g_qh + (size_t)b * 65536;
    float qp = 0.f;
    #pragma unroll
    for (int i = 0; i < 4; ++i) {
        float v[8];
        *(float4*)(v)     = *(const float4*)(src + i * 8);
        *(float4*)(v + 4) = *(const float4*)(src + i * 8 + 4);
        #pragma unroll
        for (int e = 0; e < 8; ++e) qp += v[e] * __ldg(att_w + 256 + d0 + i * 8 + e);
        uint4 hv = make_uint4(packh(v[0], v[1]), packh(v[2], v[3]),
                              packh(v[4], v[5]), packh(v[6], v[7]));
        *(uint4*)(dst + sw512(j, d0 * 2 + i * 16)) = hv;
    }
    qp += __shfl_xor_sync(0xffffffffu, qp, 1);
    qp += __shfl_xor_sync(0xffffffffu, qp, 2);
    qp += __shfl_xor_sync(0xffffffffu, qp, 4);
    if ((threadIdx.x & 7) == 0) g_qproj[b * JDIM + j] = qp;
}

__global__ __launch_bounds__(256, 1)
void bidaf_k1_mma(const float* __restrict__ ctx, const float* __restrict__ qst,
                  const int* __restrict__ con_lens, const int* __restrict__ qu_lens,
                  const float* __restrict__ att_w, float* __restrict__ G)
{
    extern __shared__ char U[];
    __shared__ float s_wc[256], s_wcq[256];
    __shared__ float s_qproj[128], s_cproj[128];
    __shared__ float s_m[128];

    const uint32_t ub = smem_to_u32(U);
    const int tid  = threadIdx.x;
    const int lane = tid & 31;
    const int warp = tid >> 5;
    const int b    = blockIdx.y;
    const int tile = blockIdx.x;
    const int t0   = tile * 128;
    const int clen = con_lens[b];
    const int qlen = qu_lens[b];

    s_wc[tid]  = att_w[tid];
    s_wcq[tid] = att_w[512 + tid];
    if (tid < 128) s_qproj[tid] = g_qproj[b * JDIM + tid];
    __syncthreads();   // weights/qproj visible before consumption

    // ---- async copy of preconverted Q (swizzle preserved byte-for-byte) -----
    {
        const unsigned char* src = g_qh + (size_t)b * 65536;
        #pragma unroll
        for (int i = 0; i < 16; ++i) {
            const uint32_t off = (uint32_t)(i * 256 + tid) * 16u;
            cp_async16(ub + QHI_OFF + off, src + off);
        }
    }
    CP_COMMIT();   // group: Q

    // ---- async prefetch of raw fp32 ctx chunk 1 into CTXRAW -----------------
    {
        #pragma unroll
        for (int k = 0; k < 16; ++k) {
            const int row = k * 8 + warp;
            const float* src = ctx + ((size_t)(t0 + row) * BDIM + b) * DDIM + 128 + lane * 4;
            cp_async16(ub + CTXRAW_OFF + (uint32_t)(row * 512 + lane * 16), src);
        }
    }
    CP_COMMIT();   // group: ctx chunk 1

    // ---- chunk 0 staging: warp=row, lane=4 consecutive floats (coalesced) ---
    #pragma unroll
    for (int k = 0; k < 16; ++k) {
        const int row = k * 8 + warp;
        const float* src = ctx + ((size_t)(t0 + row) * BDIM + b) * DDIM + lane * 4;
        float4 v = *(const float4*)src;
        const float* wc  = s_wc  + lane * 4;
        const float* wcq = s_wcq + lane * 4;
        float dot = v.x * wc[0] + v.y * wc[1] + v.z * wc[2] + v.w * wc[3];
        float m0 = v.x * wcq[0], m1 = v.y * wcq[1], m2 = v.z * wcq[2], m3 = v.w * wcq[3];
        const uint32_t off = sw256(row, lane * 8);
        *(uint2*)(U + CWHI_OFF + off) = make_uint2(packh(m0, m1), packh(m2, m3));
        #pragma unroll
        for (int o = 16; o > 0; o >>= 1) dot += __shfl_xor_sync(0xffffffffu, dot, o);
        if (lane == 0) s_cproj[row] = dot;
    }

    // fragment address components
    const int rb = warp * 16;
    const uint32_t a_row  = (uint32_t)(rb + (lane & 15));
    const uint32_t a_cb   = (uint32_t)((lane >> 4) * 16);
    const uint32_t b1_row = (uint32_t)(((lane >> 4) << 3) + (lane & 7));   // GEMM1 B
    const uint32_t b1_cb  = (uint32_t)(((lane >> 3) & 1) * 16);
    const uint32_t b2_row = (uint32_t)(lane & 15);                          // GEMM2 B (trans)
    const uint32_t b2_cb  = (uint32_t)((lane >> 4) * 16);

    float acc[16][4];
    #pragma unroll
    for (int n = 0; n < 16; ++n)
        #pragma unroll
        for (int e = 0; e < 4; ++e) acc[n][e] = 0.f;

    CP_WAIT(1);        // Q image resident (ctx chunk 1 may still be in flight)
    __syncthreads();

    // ---------------- GEMM1 chunk 0 (single-pass cw-hi) ----------------------
    #pragma unroll
    for (int ks = 0; ks < 8; ++ks) {
        uint32_t ah[4];
        ldsm4(ah, ub + CWHI_OFF + sw256((int)a_row, ks * 32 + (int)a_cb));
        #pragma unroll
        for (int nb2 = 0; nb2 < 8; ++nb2) {
            uint32_t bf[4];
            ldsm4(bf, ub + QHI_OFF + sw512(nb2 * 16 + (int)b1_row, ks * 32 + (int)b1_cb));
            mma_f16(acc[nb2 * 2],     ah, bf[0], bf[1]);
            mma_f16(acc[nb2 * 2 + 1], ah, bf[2], bf[3]);
        }
    }
    __syncthreads();   // chunk0 mma done reading CW
    CP_WAIT(0);        // raw ctx chunk 1 resident

    // ---- chunk 1 conversion from smem (no DRAM latency) ---------------------
    #pragma unroll
    for (int k = 0; k < 16; ++k) {
        const int row = k * 8 + warp;
        float4 v = *(const float4*)(U + CTXRAW_OFF + row * 512 + lane * 16);
        const float* wc  = s_wc  + 128 + lane * 4;
        const float* wcq = s_wcq + 128 + lane * 4;
        float dot = v.x * wc[0] + v.y * wc[1] + v.z * wc[2] + v.w * wc[3];
        float m0 = v.x * wcq[0], m1 = v.y * wcq[1], m2 = v.z * wcq[2], m3 = v.w * wcq[3];
        const uint32_t off = sw256(row, lane * 8);
        *(uint2*)(U + CWHI_OFF + off) = make_uint2(packh(m0, m1), packh(m2, m3));
        #pragma unroll
        for (int o = 16; o > 0; o >>= 1) dot += __shfl_xor_sync(0xffffffffu, dot, o);
        if (lane == 0) s_cproj[row] += dot;
    }
    __syncthreads();

    // ---------------- GEMM1 chunk 1 ------------------------------------------
    #pragma unroll
    for (int ks = 0; ks < 8; ++ks) {
        uint32_t ah[4];
        ldsm4(ah, ub + CWHI_OFF + sw256((int)a_row, ks * 32 + (int)a_cb));
        #pragma unroll
        for (int nb2 = 0; nb2 < 8; ++nb2) {
            uint32_t bf[4];
            ldsm4(bf, ub + QHI_OFF + sw512(nb2 * 16 + (int)b1_row, 256 + ks * 32 + (int)b1_cb));
            mma_f16(acc[nb2 * 2],     ah, bf[0], bf[1]);
            mma_f16(acc[nb2 * 2 + 1], ah, bf[2], bf[3]);
        }
    }
    __syncthreads();

    // ---------------- softmax over j in registers -----------------------------
    const int r0 = rb + (lane >> 2);
    const int r1 = r0 + 8;
    const float cpv0 = s_cproj[r0], cpv1 = s_cproj[r1];
    const bool tval0 = (t0 + r0) < clen;
    const bool tval1 = (t0 + r1) < clen;

    float mx0 = -3.4e38f, mx1 = -3.4e38f;
    #pragma unroll
    for (int nb = 0; nb < 16; ++nb) {
        const int j0 = nb * 8 + (lane & 3) * 2;
        const float2 qp = *(const float2*)&s_qproj[j0];
        const bool jv0 = j0 < qlen, jv1 = (j0 + 1) < qlen;
        float s0 = (tval0 && jv0) ? acc[nb][0] + cpv0 + qp.x : VNEG;
        float s1 = (tval0 && jv1) ? acc[nb][1] + cpv0 + qp.y : VNEG;
        float s2 = (tval1 && jv0) ? acc[nb][2] + cpv1 + qp.x : VNEG;
        float s3 = (tval1 && jv1) ? acc[nb][3] + cpv1 + qp.y : VNEG;
        acc[nb][0] = s0; acc[nb][1] = s1; acc[nb][2] = s2; acc[nb][3] = s3;
        mx0 = fmaxf(mx0, fmaxf(s0, s1));
        mx1 = fmaxf(mx1, fmaxf(s2, s3));
    }
    mx0 = fmaxf(mx0, __shfl_xor_sync(0xffffffffu, mx0, 1));
    mx0 = fmaxf(mx0, __shfl_xor_sync(0xffffffffu, mx0, 2));
    mx1 = fmaxf(mx1, __shfl_xor_sync(0xffffffffu, mx1, 1));
    mx1 = fmaxf(mx1, __shfl_xor_sync(0xffffffffu, mx1, 2));

    if ((lane & 3) == 0) { s_m[r0] = mx0; s_m[r1] = mx1; }

    float sm0 = 0.f, sm1 = 0.f;
    #pragma unroll
    for (int nb = 0; nb < 16; ++nb) {
        acc[nb][0] = __expf(acc[nb][0] - mx0); sm0 += acc[nb][0];
        acc[nb][1] = __expf(acc[nb][1] - mx0); sm0 += acc[nb][1];
        acc[nb][2] = __expf(acc[nb][2] - mx1); sm1 += acc[nb][2];
        acc[nb][3] = __expf(acc[nb][3] - mx1); sm1 += acc[nb][3];
    }
    sm0 += __shfl_xor_sync(0xffffffffu, sm0, 1);
    sm0 += __shfl_xor_sync(0xffffffffu, sm0, 2);
    sm1 += __shfl_xor_sync(0xffffffffu, sm1, 1);
    sm1 += __shfl_xor_sync(0xffffffffu, sm1, 2);
    const float iv0 = 1.f / sm0, iv1 = 1.f / sm1;

    __syncthreads();   // s_m complete

    // ---- tile-level max/sum for split softmax over t (warp-redundant) -------
    float Lb, Sw;
    {
        float v0 = s_m[lane], v1 = s_m[lane + 32], v2 = s_m[lane + 64], v3 = s_m[lane + 96];
        Lb = fmaxf(fmaxf(v0, v1), fmaxf(v2, v3));
        #pragma unroll
        for (int o = 16; o > 0; o >>= 1) Lb = fmaxf(Lb, __shfl_xor_sync(0xffffffffu, Lb, o));
        Sw = __expf(v0 - Lb) + __expf(v1 - Lb) + __expf(v2 - Lb) + __expf(v3 - Lb);
        #pragma unroll
        for (int o = 16; o > 0; o >>= 1) Sw += __shfl_xor_sync(0xffffffffu, Sw, o);
    }
    const float w0 = __expf(mx0 - Lb);
    const float w1 = __expf(mx1 - Lb);
    if (tid == 0) {
        g_pls[(b * 8 + tile) * 2]     = Lb;
        g_pls[(b * 8 + tile) * 2 + 1] = Sw;
    }

    // ---------------- pack P into A-fragments (hi fp16 only) ------------------
    uint32_t Ah[8][4];
    #pragma unroll
    for (int ks = 0; ks < 8; ++ks) {
        float p00 = acc[2 * ks][0] * iv0,     p01 = acc[2 * ks][1] * iv0;
        float p10 = acc[2 * ks][2] * iv1,     p11 = acc[2 * ks][3] * iv1;
        float p20 = acc[2 * ks + 1][0] * iv0, p21 = acc[2 * ks + 1][1] * iv0;
        float p30 = acc[2 * ks + 1][2] * iv1, p31 = acc[2 * ks + 1][3] * iv1;
        Ah[ks][0] = packh(p00, p01);
        Ah[ks][1] = packh(p10, p11);
        Ah[ks][2] = packh(p20, p21);
        Ah[ks][3] = packh(p30, p31);
    }

    // ---------------- GEMM2: c2q = Ph . Q, two 128-d halves -------------------
    const float tv0 = tval0 ? 1.f : 0.f;
    const float tv1 = tval1 ? 1.f : 0.f;
    const float* crow0 = ctx + ((size_t)(t0 + r0) * BDIM + b) * DDIM;
    const float* crow1 = ctx + ((size_t)(t0 + r1) * BDIM + b) * DDIM;
    float* grow0 = G + ((size_t)b * TDIM + t0 + r0) * (4 * DDIM);
    float* grow1 = G + ((size_t)b * TDIM + t0 + r1) * (4 * DDIM);
    const uint32_t slot = (uint32_t)(warp * 8 + (lane >> 2));

    #pragma unroll 1
    for (int h = 0; h < 2; ++h) {
        #pragma unroll
        for (int n = 0; n < 16; ++n)
            #pragma unroll
            for (int e = 0; e < 4; ++e) acc[n][e] = 0.f;

        #pragma unroll
        for (int ks = 0; ks < 8; ++ks) {
            #pragma unroll
            for (int nb2 = 0; nb2 < 8; ++nb2) {
                uint32_t bf[4];
                ldsm4t(bf, ub + QHI_OFF + sw512(ks * 16 + (int)b2_row, h * 256 + nb2 * 32 + (int)b2_cb));
                mma_f16(acc[nb2 * 2],     Ah[ks], bf[0], bf[1]);
                mma_f16(acc[nb2 * 2 + 1], Ah[ks], bf[2], bf[3]);
            }
        }

        // epilogue for this d-half: G cols [0,768) + q2c partial store
        #pragma unroll
        for (int nb = 0; nb < 16; ++nb) {
            const int d = h * 128 + nb * 8 + (lane & 3) * 2;
            float2 c0 = *(const float2*)(crow0 + d);
            float2 c1 = *(const float2*)(crow1 + d);
            float2 q0 = make_float2(acc[nb][0], acc[nb][1]);
            float2 q1 = make_float2(acc[nb][2], acc[nb][3]);
            stcs2(grow0 + d,       c0.x * tv0,        c0.y * tv0);
            stcs2(grow0 + 256 + d, q0.x * tv0,        q0.y * tv0);
            stcs2(grow0 + 512 + d, c0.x * q0.x * tv0, c0.y * q0.y * tv0);
            stcs2(grow1 + d,       c1.x * tv1,        c1.y * tv1);
            stcs2(grow1 + 256 + d, q1.x * tv1,        q1.y * tv1);
            stcs2(grow1 + 512 + d, c1.x * q1.x * tv1, c1.y * q1.y * tv1);
            float2 vp;
            vp.x = w0 * c0.x + w1 * c1.x;
            vp.y = w0 * c0.y + w1 * c1.y;
            *(float2*)(U + PART_OFF + (slot * 258 + (uint32_t)d) * 4u) = vp;
        }
    }

    // ---- reduce q2c partials over 64 slots; write per-tile vector -----------
    __syncthreads();
    float accp = 0.f;
    #pragma unroll
    for (int s = 0; s < 64; ++s)
        accp += *(const float*)(U + PART_OFF + ((uint32_t)s * 258 + (uint32_t)tid) * 4u);
    g_pvec[((size_t)(b * 8 + tile)) * DDIM + tid] = accp;
}

// ---- k2: combine per-tile partials -> q2c (split softmax over t) ----
__global__ __launch_bounds__(256, 1)
void bidaf_k2(int dummy)
{
    const int b = blockIdx.x;
    const int tid = threadIdx.x;
    float L[8], S[8];
    #pragma unroll
    for (int i = 0; i < 8; ++i) {
        L[i] = g_pls[(b * 8 + i) * 2];
        S[i] = g_pls[(b * 8 + i) * 2 + 1];
    }
    float M = L[0];
    #pragma unroll
    for (int i = 1; i < 8; ++i) M = fmaxf(M, L[i]);
    float denom = 0.f, sc[8];
    #pragma unroll
    for (int i = 0; i < 8; ++i) { sc[i] = __expf(L[i] - M); denom += sc[i] * S[i]; }
    float acc = 0.f;
    #pragma unroll
    for (int i = 0; i < 8; ++i)
        acc += sc[i] * g_pvec[((size_t)(b * 8 + i)) * DDIM + tid];
    g_q2c[b * DDIM + tid] = acc / denom;
}

// ---- k3: G[:, 768:1024) = ctx * q2c * t_valid ----
__global__ void bidaf_k3(const float* __restrict__ ctx, const int* __restrict__ con_lens,
                         float* __restrict__ G)
{
    const int gid = blockIdx.x * 256 + threadIdx.x;
    const int r = gid >> 6;
    const int d = (gid & 63) * 4;
    const int b = r >> 10;
    const int t = r & (TDIM - 1);
    const float tv = (t < con_lens[b]) ? 1.f : 0.f;
    float4 c = *(const float4*)&ctx[((size_t)t * BDIM + b) * DDIM + d];
    float4 q = *(const float4*)&g_q2c[b * DDIM + d];
    float4 o;
    o.x = c.x * q.x * tv; o.y = c.y * q.y * tv;
    o.z = c.z * q.z * tv; o.w = c.w * q.w * tv;
    stcs4(&G[(size_t)r * (4 * DDIM) + 3 * DDIM + d], o);
}

extern "C" void kernel_launch(void* const* d_in, const int* in_sizes, int n_in,
                              void* d_out, int out_size)
{
    const float* ctx = (const float*)d_in[0];
    const float* qst = (const float*)d_in[1];
    const int*   cl  = (const int*)d_in[2];
    const int*   ql  = (const int*)d_in[3];
    const float* aw  = (const float*)d_in[4];
    float* G = (float*)d_out;

    cudaFuncSetAttribute(bidaf_k1_mma, cudaFuncAttributeMaxDynamicSharedMemorySize, SMEM_DYN);

    bidaf_k0<<<dim3(4, BDIM), 256>>>(qst, aw);
    dim3 g1(TDIM / 128, BDIM);
    bidaf_k1_mma<<<g1, 256, SMEM_DYN>>>(ctx, qst, cl, ql, aw, G);
    bidaf_k2<<<BDIM, 256>>>(0);
    bidaf_k3<<<(BDIM * TDIM * DDIM / 4) / 256, 256>>>(ctx, cl, G);
}

// round 17
// speedup vs baseline: 1.1887x; 1.0410x over previous
#include <cuda_runtime.h>
#include <cuda_fp16.h>
#include <cstdint>

#define TDIM 1024
#define JDIM 128
#define BDIM 32
#define DDIM 256
#define VNEG -1e30f

// ---------------- scratch ----------------
__device__ float g_q2c[BDIM * DDIM];
__device__ __align__(16) unsigned char g_qh[BDIM * 65536];   // preconverted swizzled Q fp16
__device__ float g_qproj[BDIM * JDIM];
__device__ float g_pvec[BDIM * 8 * DDIM];    // per-tile weighted ctx partials
__device__ float g_pls[BDIM * 8 * 2];        // per-tile (L, S)

// ---------------- PTX helpers ----------------
__device__ __forceinline__ void ldsm4(uint32_t* r, uint32_t addr) {
    asm volatile("ldmatrix.sync.aligned.m8n8.x4.shared.b16 {%0,%1,%2,%3}, [%4];"
        : "=r"(r[0]), "=r"(r[1]), "=r"(r[2]), "=r"(r[3]) : "r"(addr));
}
__device__ __forceinline__ void ldsm4t(uint32_t* r, uint32_t addr) {
    asm volatile("ldmatrix.sync.aligned.m8n8.x4.trans.shared.b16 {%0,%1,%2,%3}, [%4];"
        : "=r"(r[0]), "=r"(r[1]), "=r"(r[2]), "=r"(r[3]) : "r"(addr));
}
__device__ __forceinline__ void mma_f16(float* d, const uint32_t* a, uint32_t b0, uint32_t b1) {
    asm volatile("mma.sync.aligned.m16n8k16.row.col.f32.f16.f16.f32 "
        "{%0,%1,%2,%3}, {%4,%5,%6,%7}, {%8,%9}, {%0,%1,%2,%3};"
        : "+f"(d[0]), "+f"(d[1]), "+f"(d[2]), "+f"(d[3])
        : "r"(a[0]), "r"(a[1]), "r"(a[2]), "r"(a[3]), "r"(b0), "r"(b1));
}
__device__ __forceinline__ uint32_t smem_to_u32(const void* p) {
    uint32_t a;
    asm("{ .reg .u64 t; cvta.to.shared.u64 t, %1; cvt.u32.u64 %0, t; }" : "=r"(a) : "l"(p));
    return a;
}
__device__ __forceinline__ void cp_async16(uint32_t dst, const void* src) {
    asm volatile("cp.async.cg.shared.global [%0], [%1], 16;" :: "r"(dst), "l"(src));
}
#define CP_COMMIT() asm volatile("cp.async.commit_group;" ::: "memory")
#define CP_WAIT(n)  asm volatile("cp.async.wait_group %0;" :: "n"(n) : "memory")

__device__ __forceinline__ uint32_t packh(float a, float b) {
    __half2 h = __floats2half2_rn(a, b);     // a -> low 16 bits
    return *reinterpret_cast<uint32_t*>(&h);
}

// streaming (evict-first) stores: G is write-once, keep ctx resident in L2
__device__ __forceinline__ void stcs2(float* p, float x, float y) {
    asm volatile("st.global.cs.v2.f32 [%0], {%1, %2};" :: "l"(p), "f"(x), "f"(y) : "memory");
}
__device__ __forceinline__ void stcs4(float* p, float4 v) {
    asm volatile("st.global.cs.v4.f32 [%0], {%1, %2, %3, %4};"
        :: "l"(p), "f"(v.x), "f"(v.y), "f"(v.z), "f"(v.w) : "memory");
}

// swizzled byte offsets (XOR within 128B blocks)
__device__ __forceinline__ uint32_t sw512(int row, int colb) {   // 512B rows (Q: 256 fp16)
    return (uint32_t)(row * 512 + (colb & ~127) + ((colb & 127) ^ ((row & 7) << 4)));
}
__device__ __forceinline__ uint32_t sw256(int row, int colb) {   // 256B rows (cw chunk: 128 fp16)
    return (uint32_t)(row * 256 + (colb & ~127) + ((colb & 127) ^ ((row & 7) << 4)));
}

// dynamic smem layout (bytes):
//   QHI    [0, 64K)          swizzled Q fp16
//   CWHI   [64K, 96K)        cw chunk fp16 (128 rows x 128 cols)
//   CTXRAW [96K, 164K)       raw fp32 ctx cols 128..255, row stride 544B (bank-rotated)
//   PART   [164K, 197K)      q2c partials, 32 slots x 264-float stride (own region)
#define QHI_OFF      0
#define CWHI_OFF     65536
#define CTXRAW_OFF   98304
#define CTXRAW_STR   544
#define PART_OFF     167936
#define PART_STR     264
#define SMEM_DYN     201728

// ---- k0: preconvert Q -> swizzled fp16 (per batch) + qproj ---------------
__global__ __launch_bounds__(256, 1)
void bidaf_k0(const float* __restrict__ qst, const float* __restrict__ att_w)
{
    const int b  = blockIdx.y;
    const int j  = blockIdx.x * 32 + (threadIdx.x >> 3);
    const int d0 = (threadIdx.x & 7) * 32;
    const float* src = qst + ((size_t)j * BDIM + b) * DDIM + d0;
    unsigned char* dst = g_qh + (size_t)b * 65536;
    float qp = 0.f;
    #pragma unroll
    for (int i = 0; i < 4; ++i) {
        float v[8];
        *(float4*)(v)     = *(const float4*)(src + i * 8);
        *(float4*)(v + 4) = *(const float4*)(src + i * 8 + 4);
        #pragma unroll
        for (int e = 0; e < 8; ++e) qp += v[e] * __ldg(att_w + 256 + d0 + i * 8 + e);
        uint4 hv = make_uint4(packh(v[0], v[1]), packh(v[2], v[3]),
                              packh(v[4], v[5]), packh(v[6], v[7]));
        *(uint4*)(dst + sw512(j, d0 * 2 + i * 16)) = hv;
    }
    qp += __shfl_xor_sync(0xffffffffu, qp, 1);
    qp += __shfl_xor_sync(0xffffffffu, qp, 2);
    qp += __shfl_xor_sync(0xffffffffu, qp, 4);
    if ((threadIdx.x & 7) == 0) g_qproj[b * JDIM + j] = qp;
}

__global__ __launch_bounds__(256, 1)
void bidaf_k1_mma(const float* __restrict__ ctx, const float* __restrict__ qst,
                  const int* __restrict__ con_lens, const int* __restrict__ qu_lens,
                  const float* __restrict__ att_w, float* __restrict__ G)
{
    extern __shared__ char U[];
    __shared__ float s_wc[256], s_wcq[256];
    __shared__ float s_qproj[128], s_cproj[128];
    __shared__ float s_m[128];

    const uint32_t ub = smem_to_u32(U);
    const int tid  = threadIdx.x;
    const int lane = tid & 31;
    const int warp = tid >> 5;
    const int b    = blockIdx.y;
    const int tile = blockIdx.x;
    const int t0   = tile * 128;
    const int clen = con_lens[b];
    const int qlen = qu_lens[b];

    s_wc[tid]  = att_w[tid];
    s_wcq[tid] = att_w[512 + tid];
    if (tid < 128) s_qproj[tid] = g_qproj[b * JDIM + tid];
    __syncthreads();   // weights/qproj visible before consumption

    // ---- async copy of preconverted Q (swizzle preserved byte-for-byte) -----
    {
        const unsigned char* src = g_qh + (size_t)b * 65536;
        #pragma unroll
        for (int i = 0; i < 16; ++i) {
            const uint32_t off = (uint32_t)(i * 256 + tid) * 16u;
            cp_async16(ub + QHI_OFF + off, src + off);
        }
    }
    CP_COMMIT();   // group: Q

    // ---- async prefetch of raw fp32 ctx chunk 1 into CTXRAW (544B stride) ---
    {
        #pragma unroll
        for (int k = 0; k < 16; ++k) {
            const int row = k * 8 + warp;
            const float* src = ctx + ((size_t)(t0 + row) * BDIM + b) * DDIM + 128 + lane * 4;
            cp_async16(ub + CTXRAW_OFF + (uint32_t)(row * CTXRAW_STR + lane * 16), src);
        }
    }
    CP_COMMIT();   // group: ctx chunk 1

    // ---- chunk 0 staging: warp=row, lane=4 consecutive floats (coalesced) ---
    #pragma unroll
    for (int k = 0; k < 16; ++k) {
        const int row = k * 8 + warp;
        const float* src = ctx + ((size_t)(t0 + row) * BDIM + b) * DDIM + lane * 4;
        float4 v = *(const float4*)src;
        const float* wc  = s_wc  + lane * 4;
        const float* wcq = s_wcq + lane * 4;
        float dot = v.x * wc[0] + v.y * wc[1] + v.z * wc[2] + v.w * wc[3];
        float m0 = v.x * wcq[0], m1 = v.y * wcq[1], m2 = v.z * wcq[2], m3 = v.w * wcq[3];
        const uint32_t off = sw256(row, lane * 8);
        *(uint2*)(U + CWHI_OFF + off) = make_uint2(packh(m0, m1), packh(m2, m3));
        #pragma unroll
        for (int o = 16; o > 0; o >>= 1) dot += __shfl_xor_sync(0xffffffffu, dot, o);
        if (lane == 0) s_cproj[row] = dot;
    }

    // fragment address components
    const int rb = warp * 16;
    const uint32_t a_row  = (uint32_t)(rb + (lane & 15));
    const uint32_t a_cb   = (uint32_t)((lane >> 4) * 16);
    const uint32_t b1_row = (uint32_t)(((lane >> 4) << 3) + (lane & 7));   // GEMM1 B
    const uint32_t b1_cb  = (uint32_t)(((lane >> 3) & 1) * 16);
    const uint32_t b2_row = (uint32_t)(lane & 15);                          // GEMM2 B (trans)
    const uint32_t b2_cb  = (uint32_t)((lane >> 4) * 16);

    float acc[16][4];
    #pragma unroll
    for (int n = 0; n < 16; ++n)
        #pragma unroll
        for (int e = 0; e < 4; ++e) acc[n][e] = 0.f;

    CP_WAIT(1);        // Q image resident (ctx chunk 1 may still be in flight)
    __syncthreads();

    // ---------------- GEMM1 chunk 0 (single-pass cw-hi) ----------------------
    #pragma unroll
    for (int ks = 0; ks < 8; ++ks) {
        uint32_t ah[4];
        ldsm4(ah, ub + CWHI_OFF + sw256((int)a_row, ks * 32 + (int)a_cb));
        #pragma unroll
        for (int nb2 = 0; nb2 < 8; ++nb2) {
            uint32_t bf[4];
            ldsm4(bf, ub + QHI_OFF + sw512(nb2 * 16 + (int)b1_row, ks * 32 + (int)b1_cb));
            mma_f16(acc[nb2 * 2],     ah, bf[0], bf[1]);
            mma_f16(acc[nb2 * 2 + 1], ah, bf[2], bf[3]);
        }
    }
    __syncthreads();   // chunk0 mma done reading CW
    CP_WAIT(0);        // raw ctx chunk 1 resident

    // ---- chunk 1 conversion from smem (no DRAM latency) ---------------------
    #pragma unroll
    for (int k = 0; k < 16; ++k) {
        const int row = k * 8 + warp;
        float4 v = *(const float4*)(U + CTXRAW_OFF + row * CTXRAW_STR + lane * 16);
        const float* wc  = s_wc  + 128 + lane * 4;
        const float* wcq = s_wcq + 128 + lane * 4;
        float dot = v.x * wc[0] + v.y * wc[1] + v.z * wc[2] + v.w * wc[3];
        float m0 = v.x * wcq[0], m1 = v.y * wcq[1], m2 = v.z * wcq[2], m3 = v.w * wcq[3];
        const uint32_t off = sw256(row, lane * 8);
        *(uint2*)(U + CWHI_OFF + off) = make_uint2(packh(m0, m1), packh(m2, m3));
        #pragma unroll
        for (int o = 16; o > 0; o >>= 1) dot += __shfl_xor_sync(0xffffffffu, dot, o);
        if (lane == 0) s_cproj[row] += dot;
    }
    __syncthreads();

    // ---------------- GEMM1 chunk 1 ------------------------------------------
    #pragma unroll
    for (int ks = 0; ks < 8; ++ks) {
        uint32_t ah[4];
        ldsm4(ah, ub + CWHI_OFF + sw256((int)a_row, ks * 32 + (int)a_cb));
        #pragma unroll
        for (int nb2 = 0; nb2 < 8; ++nb2) {
            uint32_t bf[4];
            ldsm4(bf, ub + QHI_OFF + sw512(nb2 * 16 + (int)b1_row, 256 + ks * 32 + (int)b1_cb));
            mma_f16(acc[nb2 * 2],     ah, bf[0], bf[1]);
            mma_f16(acc[nb2 * 2 + 1], ah, bf[2], bf[3]);
        }
    }
    __syncthreads();

    // ---------------- softmax over j in registers -----------------------------
    const int r0 = rb + (lane >> 2);
    const int r1 = r0 + 8;
    const float cpv0 = s_cproj[r0], cpv1 = s_cproj[r1];
    const bool tval0 = (t0 + r0) < clen;
    const bool tval1 = (t0 + r1) < clen;

    float mx0 = -3.4e38f, mx1 = -3.4e38f;
    #pragma unroll
    for (int nb = 0; nb < 16; ++nb) {
        const int j0 = nb * 8 + (lane & 3) * 2;
        const float2 qp = *(const float2*)&s_qproj[j0];
        const bool jv0 = j0 < qlen, jv1 = (j0 + 1) < qlen;
        float s0 = (tval0 && jv0) ? acc[nb][0] + cpv0 + qp.x : VNEG;
        float s1 = (tval0 && jv1) ? acc[nb][1] + cpv0 + qp.y : VNEG;
        float s2 = (tval1 && jv0) ? acc[nb][2] + cpv1 + qp.x : VNEG;
        float s3 = (tval1 && jv1) ? acc[nb][3] + cpv1 + qp.y : VNEG;
        acc[nb][0] = s0; acc[nb][1] = s1; acc[nb][2] = s2; acc[nb][3] = s3;
        mx0 = fmaxf(mx0, fmaxf(s0, s1));
        mx1 = fmaxf(mx1, fmaxf(s2, s3));
    }
    mx0 = fmaxf(mx0, __shfl_xor_sync(0xffffffffu, mx0, 1));
    mx0 = fmaxf(mx0, __shfl_xor_sync(0xffffffffu, mx0, 2));
    mx1 = fmaxf(mx1, __shfl_xor_sync(0xffffffffu, mx1, 1));
    mx1 = fmaxf(mx1, __shfl_xor_sync(0xffffffffu, mx1, 2));

    if ((lane & 3) == 0) { s_m[r0] = mx0; s_m[r1] = mx1; }

    float sm0 = 0.f, sm1 = 0.f;
    #pragma unroll
    for (int nb = 0; nb < 16; ++nb) {
        acc[nb][0] = __expf(acc[nb][0] - mx0); sm0 += acc[nb][0];
        acc[nb][1] = __expf(acc[nb][1] - mx0); sm0 += acc[nb][1];
        acc[nb][2] = __expf(acc[nb][2] - mx1); sm1 += acc[nb][2];
        acc[nb][3] = __expf(acc[nb][3] - mx1); sm1 += acc[nb][3];
    }
    sm0 += __shfl_xor_sync(0xffffffffu, sm0, 1);
    sm0 += __shfl_xor_sync(0xffffffffu, sm0, 2);
    sm1 += __shfl_xor_sync(0xffffffffu, sm1, 1);
    sm1 += __shfl_xor_sync(0xffffffffu, sm1, 2);
    const float iv0 = 1.f / sm0, iv1 = 1.f / sm1;

    __syncthreads();   // s_m complete

    // ---- tile-level max/sum for split softmax over t (warp-redundant) -------
    float Lb, Sw;
    {
        float v0 = s_m[lane], v1 = s_m[lane + 32], v2 = s_m[lane + 64], v3 = s_m[lane + 96];
        Lb = fmaxf(fmaxf(v0, v1), fmaxf(v2, v3));
        #pragma unroll
        for (int o = 16; o > 0; o >>= 1) Lb = fmaxf(Lb, __shfl_xor_sync(0xffffffffu, Lb, o));
        Sw = __expf(v0 - Lb) + __expf(v1 - Lb) + __expf(v2 - Lb) + __expf(v3 - Lb);
        #pragma unroll
        for (int o = 16; o > 0; o >>= 1) Sw += __shfl_xor_sync(0xffffffffu, Sw, o);
    }
    const float w0 = __expf(mx0 - Lb);
    const float w1 = __expf(mx1 - Lb);
    if (tid == 0) {
        g_pls[(b * 8 + tile) * 2]     = Lb;
        g_pls[(b * 8 + tile) * 2 + 1] = Sw;
    }

    // ---------------- pack P into A-fragments (hi fp16 only) ------------------
    uint32_t Ah[8][4];
    #pragma unroll
    for (int ks = 0; ks < 8; ++ks) {
        float p00 = acc[2 * ks][0] * iv0,     p01 = acc[2 * ks][1] * iv0;
        float p10 = acc[2 * ks][2] * iv1,     p11 = acc[2 * ks][3] * iv1;
        float p20 = acc[2 * ks + 1][0] * iv0, p21 = acc[2 * ks + 1][1] * iv0;
        float p30 = acc[2 * ks + 1][2] * iv1, p31 = acc[2 * ks + 1][3] * iv1;
        Ah[ks][0] = packh(p00, p01);
        Ah[ks][1] = packh(p10, p11);
        Ah[ks][2] = packh(p20, p21);
        Ah[ks][3] = packh(p30, p31);
    }

    // ---------------- GEMM2: c2q = Ph . Q, two 128-d halves -------------------
    // Epilogue: G stores (streaming) + q2c partials (32 combined slots).
    // h=1 ctx rows are read from CTXRAW smem (still intact: PART is separate).
    const float tv0 = tval0 ? 1.f : 0.f;
    const float tv1 = tval1 ? 1.f : 0.f;
    const float* crow0 = ctx + ((size_t)(t0 + r0) * BDIM + b) * DDIM;
    const float* crow1 = ctx + ((size_t)(t0 + r1) * BDIM + b) * DDIM;
    float* grow0 = G + ((size_t)b * TDIM + t0 + r0) * (4 * DDIM);
    float* grow1 = G + ((size_t)b * TDIM + t0 + r1) * (4 * DDIM);
    const uint32_t slot = (uint32_t)(warp * 4 + (lane >> 3));   // 0..31

    #pragma unroll 1
    for (int h = 0; h < 2; ++h) {
        #pragma unroll
        for (int n = 0; n < 16; ++n)
            #pragma unroll
            for (int e = 0; e < 4; ++e) acc[n][e] = 0.f;

        #pragma unroll
        for (int ks = 0; ks < 8; ++ks) {
            #pragma unroll
            for (int nb2 = 0; nb2 < 8; ++nb2) {
                uint32_t bf[4];
                ldsm4t(bf, ub + QHI_OFF + sw512(ks * 16 + (int)b2_row, h * 256 + nb2 * 32 + (int)b2_cb));
                mma_f16(acc[nb2 * 2],     Ah[ks], bf[0], bf[1]);
                mma_f16(acc[nb2 * 2 + 1], Ah[ks], bf[2], bf[3]);
            }
        }

        // epilogue for this d-half: G cols [0,768) + q2c partial store
        #pragma unroll
        for (int nb = 0; nb < 16; ++nb) {
            const int dl = nb * 8 + (lane & 3) * 2;
            const int d  = h * 128 + dl;
            float2 c0, c1;
            if (h == 0) {
                c0 = *(const float2*)(crow0 + d);
                c1 = *(const float2*)(crow1 + d);
            } else {
                c0 = *(const float2*)(U + CTXRAW_OFF + r0 * CTXRAW_STR + dl * 4);
                c1 = *(const float2*)(U + CTXRAW_OFF + r1 * CTXRAW_STR + dl * 4);
            }
            float2 q0 = make_float2(acc[nb][0], acc[nb][1]);
            float2 q1 = make_float2(acc[nb][2], acc[nb][3]);
            stcs2(grow0 + d,       c0.x * tv0,        c0.y * tv0);
            stcs2(grow0 + 256 + d, q0.x * tv0,        q0.y * tv0);
            stcs2(grow0 + 512 + d, c0.x * q0.x * tv0, c0.y * q0.y * tv0);
            stcs2(grow1 + d,       c1.x * tv1,        c1.y * tv1);
            stcs2(grow1 + 256 + d, q1.x * tv1,        q1.y * tv1);
            stcs2(grow1 + 512 + d, c1.x * q1.x * tv1, c1.y * q1.y * tv1);
            float2 vp;
            vp.x = w0 * c0.x + w1 * c1.x;
            vp.y = w0 * c0.y + w1 * c1.y;
            vp.x += __shfl_xor_sync(0xffffffffu, vp.x, 4);   // combine rowgroup pairs
            vp.y += __shfl_xor_sync(0xffffffffu, vp.y, 4);
            if ((lane & 4) == 0)
                *(float2*)(U + PART_OFF + ((slot * PART_STR) + (uint32_t)d) * 4u) = vp;
        }
    }

    // ---- reduce q2c partials over 32 slots; write per-tile vector -----------
    __syncthreads();
    float accp = 0.f;
    #pragma unroll
    for (int s = 0; s < 32; ++s)
        accp += *(const float*)(U + PART_OFF + ((uint32_t)s * PART_STR + (uint32_t)tid) * 4u);
    g_pvec[((size_t)(b * 8 + tile)) * DDIM + tid] = accp;
}

// ---- k2: combine per-tile partials -> q2c (split softmax over t) ----
__global__ __launch_bounds__(256, 1)
void bidaf_k2(int dummy)
{
    const int b = blockIdx.x;
    const int tid = threadIdx.x;
    float L[8], S[8];
    #pragma unroll
    for (int i = 0; i < 8; ++i) {
        L[i] = g_pls[(b * 8 + i) * 2];
        S[i] = g_pls[(b * 8 + i) * 2 + 1];
    }
    float M = L[0];
    #pragma unroll
    for (int i = 1; i < 8; ++i) M = fmaxf(M, L[i]);
    float denom = 0.f, sc[8];
    #pragma unroll
    for (int i = 0; i < 8; ++i) { sc[i] = __expf(L[i] - M); denom += sc[i] * S[i]; }
    float acc = 0.f;
    #pragma unroll
    for (int i = 0; i < 8; ++i)
        acc += sc[i] * g_pvec[((size_t)(b * 8 + i)) * DDIM + tid];
    g_q2c[b * DDIM + tid] = acc / denom;
}

// ---- k3: G[:, 768:1024) = ctx * q2c * t_valid ----
__global__ void bidaf_k3(const float* __restrict__ ctx, const int* __restrict__ con_lens,
                         float* __restrict__ G)
{
    const int gid = blockIdx.x * 256 + threadIdx.x;
    const int r = gid >> 6;
    const int d = (gid & 63) * 4;
    const int b = r >> 10;
    const int t = r & (TDIM - 1);
    const float tv = (t < con_lens[b]) ? 1.f : 0.f;
    float4 c = *(const float4*)&ctx[((size_t)t * BDIM + b) * DDIM + d];
    float4 q = *(const float4*)&g_q2c[b * DDIM + d];
    float4 o;
    o.x = c.x * q.x * tv; o.y = c.y * q.y * tv;
    o.z = c.z * q.z * tv; o.w = c.w * q.w * tv;
    stcs4(&G[(size_t)r * (4 * DDIM) + 3 * DDIM + d], o);
}

extern "C" void kernel_launch(void* const* d_in, const int* in_sizes, int n_in,
                              void* d_out, int out_size)
{
    const float* ctx = (const float*)d_in[0];
    const float* qst = (const float*)d_in[1];
    const int*   cl  = (const int*)d_in[2];
    const int*   ql  = (const int*)d_in[3];
    const float* aw  = (const float*)d_in[4];
    float* G = (float*)d_out;

    cudaFuncSetAttribute(bidaf_k1_mma, cudaFuncAttributeMaxDynamicSharedMemorySize, SMEM_DYN);

    bidaf_k0<<<dim3(4, BDIM), 256>>>(qst, aw);
    dim3 g1(TDIM / 128, BDIM);
    bidaf_k1_mma<<<g1, 256, SMEM_DYN>>>(ctx, qst, cl, ql, aw, G);
    bidaf_k2<<<BDIM, 256>>>(0);
    bidaf_k3<<<(BDIM * TDIM * DDIM / 4) / 256, 256>>>(ctx, cl, G);
}